// round 15
// baseline (speedup 1.0000x reference)
#include <cuda_runtime.h>
#include <cuda_bf16.h>
#include <cstdint>

// Problem shape (fixed): B=4, S=1024, E=1024, H=16, D=64
#define BB 4
#define SS 1024
#define EE 1024
#define HH 16
#define DD 64

// ---------------------------------------------------------------------------
// Scratch (static __device__ globals — allocation-free per harness rules)
// ---------------------------------------------------------------------------
__device__ float g_Q[BB * SS * EE];
__device__ float g_K[BB * SS * EE];
__device__ float g_V[BB * SS * EE];
__device__ float g_A[BB * SS * EE];

// ---------------------------------------------------------------------------
// Helpers
// ---------------------------------------------------------------------------
__device__ __forceinline__ uint32_t smem_u32(const void* p) {
    uint32_t a;
    asm("{ .reg .u64 t; cvta.to.shared.u64 t, %1; cvt.u32.u64 %0, t; }"
        : "=r"(a) : "l"(p));
    return a;
}

__device__ __forceinline__ uint32_t f2tf32(float f) {
    uint32_t r;
    asm("cvt.rna.tf32.f32 %0, %1;" : "=r"(r) : "f"(f));
    return r;
}

// mma.sync m16n8k8 tf32: D(f32) += A(tf32) * B(tf32)
__device__ __forceinline__ void mma_tf32(float* c, const uint32_t* a, const uint32_t* b) {
    asm volatile(
        "mma.sync.aligned.m16n8k8.row.col.f32.tf32.tf32.f32 "
        "{%0,%1,%2,%3}, {%4,%5,%6,%7}, {%8,%9}, {%0,%1,%2,%3};"
        : "+f"(c[0]), "+f"(c[1]), "+f"(c[2]), "+f"(c[3])
        : "r"(a[0]), "r"(a[1]), "r"(a[2]), "r"(a[3]),
          "r"(b[0]), "r"(b[1]));
}

// ldmatrix x4 (non-trans). Within each matrix, lane l gets (row l>>2, f32col l&3).
__device__ __forceinline__ void ldsm4(uint32_t& r0, uint32_t& r1,
                                      uint32_t& r2, uint32_t& r3, uint32_t addr) {
    asm volatile(
        "ldmatrix.sync.aligned.m8n8.x4.shared.b16 {%0,%1,%2,%3}, [%4];"
        : "=r"(r0), "=r"(r1), "=r"(r2), "=r"(r3) : "r"(addr));
}

__device__ __forceinline__ void cp16(uint32_t dst, const void* src) {
    asm volatile("cp.async.cg.shared.global [%0], [%1], 16;"
                 :: "r"(dst), "l"(src));
}
__device__ __forceinline__ void cp_commit() {
    asm volatile("cp.async.commit_group;");
}
__device__ __forceinline__ void cp_wait0() {
    asm volatile("cp.async.wait_group 0;" ::: "memory");
}
__device__ __forceinline__ void cp_wait1() {
    asm volatile("cp.async.wait_group 1;" ::: "memory");
}

// FMA-pipe exp2 for x <= 0 (clamped at -126). ~4e-5 abs err.
__device__ __forceinline__ float fexp2(float x) {
    x = fmaxf(x, -126.0f);
    float z = x + 12582912.0f;
    int   i = __float_as_int(z);
    float f = x - (z - 12582912.0f);
    float p = 9.6181e-3f;
    p = fmaf(p, f, 5.55041e-2f);
    p = fmaf(p, f, 2.402265e-1f);
    p = fmaf(p, f, 6.931472e-1f);
    p = fmaf(p, f, 1.0f);
    return __int_as_float(__float_as_int(p) + (i << 23));
}

// ---------------------------------------------------------------------------
// GEMM v4:  Y[M,N] = X[M,K] @ W[N,K]^T + bias[N]
// CTA 128x128 (grid 256 -> all 148 SMs busy), 8 warps (2m x 4n) of 64x32
// -> 64 accum regs -> 2 CTAs/SM. BK=32, cp.async TRIPLE buffer (110.6KB).
// ---------------------------------------------------------------------------
#define BM3 128
#define BN3 128
#define BK3 32
#define LD3 36

#define G3_ABUF (BM3 * LD3)                    // 4608 u32
#define G3_BBUF (BN3 * LD3)                    // 4608 u32
#define G3_STAGE (G3_ABUF + G3_BBUF)           // 9216 u32
#define G3_SMEM_BYTES (3 * G3_STAGE * 4)       // 110592 B

__global__ __launch_bounds__(256, 2) void gemm2_tf32(
    const float* __restrict__ X, const float* __restrict__ W,
    const float* __restrict__ bias, float* __restrict__ Y,
    int M, int N, int K)
{
    extern __shared__ uint32_t smg[];
    const uint32_t sb = smem_u32(smg);

    const int tid = threadIdx.x;
    const int wid = tid >> 5;
    const int lane = tid & 31;
    const int lq = lane >> 2;
    const int lr = lane & 3;

    const int wm = (wid >> 2) * 64;     // 0,64
    const int wn = (wid & 3) * 32;      // 0,32,64,96

    const int row0 = blockIdx.y * BM3;
    const int col0 = blockIdx.x * BN3;

    float c[4][4][4];
#pragma unroll
    for (int m = 0; m < 4; m++)
#pragma unroll
        for (int n = 0; n < 4; n++)
#pragma unroll
            for (int f = 0; f < 4; f++) c[m][n][f] = 0.f;

    // loader mapping: 256 threads, tile 128x32 floats, 4 iters each for A and B
    const int lrow = tid >> 3;          // 0..31
    const int lc4  = (tid & 7) * 4;     // 0..28

    // ldmatrix lane address components
    const int aRow = wm + (lane & 15);
    const int aCol = (lane >> 4) * 4;
    const int bRow = wn + ((lane >> 4) << 3) + (lane & 7);
    const int bCol = ((lane >> 3) & 1) * 4;

    const int nstages = K / BK3;        // 32

    // prologue: stages 0 and 1
#pragma unroll
    for (int ps = 0; ps < 2; ps++) {
        const int k0 = ps * BK3;
        const uint32_t ab = sb + (uint32_t)(ps * G3_STAGE) * 4;
#pragma unroll
        for (int i = 0; i < 4; i++) {
            const int r = lrow + i * 32;
            cp16(ab + (uint32_t)(r * LD3 + lc4) * 4,
                 &X[(size_t)(row0 + r) * K + k0 + lc4]);
        }
#pragma unroll
        for (int i = 0; i < 4; i++) {
            const int r = lrow + i * 32;
            cp16(ab + (uint32_t)(G3_ABUF + r * LD3 + lc4) * 4,
                 &W[(size_t)(col0 + r) * K + k0 + lc4]);
        }
        cp_commit();
    }

    int cur = 0;   // s % 3
    int nx2 = 2;   // (s+2) % 3
#pragma unroll 1
    for (int s = 0; s < nstages; s++) {
        if (s == nstages - 1) cp_wait0(); else cp_wait1();
        __syncthreads();

        if (s + 2 < nstages) {
            const int k0 = (s + 2) * BK3;
            const uint32_t ab = sb + (uint32_t)(nx2 * G3_STAGE) * 4;
#pragma unroll
            for (int i = 0; i < 4; i++) {
                const int r = lrow + i * 32;
                cp16(ab + (uint32_t)(r * LD3 + lc4) * 4,
                     &X[(size_t)(row0 + r) * K + k0 + lc4]);
            }
#pragma unroll
            for (int i = 0; i < 4; i++) {
                const int r = lrow + i * 32;
                cp16(ab + (uint32_t)(G3_ABUF + r * LD3 + lc4) * 4,
                     &W[(size_t)(col0 + r) * K + k0 + lc4]);
            }
            cp_commit();
        }

        const uint32_t abase = sb + (uint32_t)(cur * G3_STAGE) * 4;
        const uint32_t bbase = abase + (uint32_t)G3_ABUF * 4;

#pragma unroll
        for (int kk = 0; kk < 4; kk++) {
            const int k8 = kk * 8;
            uint32_t a[4][4], bf[4][2];
#pragma unroll
            for (int m = 0; m < 4; m++) {
                uint32_t r0, r1, r2, r3;
                ldsm4(r0, r1, r2, r3,
                      abase + (uint32_t)((aRow + m * 16) * LD3 + k8 + aCol) * 4);
                a[m][0] = f2tf32(__uint_as_float(r0));
                a[m][1] = f2tf32(__uint_as_float(r1));
                a[m][2] = f2tf32(__uint_as_float(r2));
                a[m][3] = f2tf32(__uint_as_float(r3));
            }
#pragma unroll
            for (int p = 0; p < 2; p++) {
                uint32_t r0, r1, r2, r3;
                ldsm4(r0, r1, r2, r3,
                      bbase + (uint32_t)((bRow + p * 16) * LD3 + k8 + bCol) * 4);
                bf[2 * p][0]     = f2tf32(__uint_as_float(r0));
                bf[2 * p][1]     = f2tf32(__uint_as_float(r1));
                bf[2 * p + 1][0] = f2tf32(__uint_as_float(r2));
                bf[2 * p + 1][1] = f2tf32(__uint_as_float(r3));
            }
#pragma unroll
            for (int m = 0; m < 4; m++)
#pragma unroll
                for (int n = 0; n < 4; n++)
                    mma_tf32(c[m][n], a[m], bf[n]);
        }

        cur = (cur == 2) ? 0 : cur + 1;
        nx2 = (nx2 == 2) ? 0 : nx2 + 1;
    }

    // epilogue: fused bias
#pragma unroll
    for (int m = 0; m < 4; m++) {
        const int r_lo = row0 + wm + m * 16 + lq;
        const int r_hi = r_lo + 8;
#pragma unroll
        for (int n = 0; n < 4; n++) {
            const int col = col0 + wn + n * 8 + lr * 2;
            const float b0 = bias[col];
            const float b1 = bias[col + 1];
            *(float2*)&Y[(size_t)r_lo * N + col] =
                make_float2(c[m][n][0] + b0, c[m][n][1] + b1);
            *(float2*)&Y[(size_t)r_hi * N + col] =
                make_float2(c[m][n][2] + b0, c[m][n][3] + b1);
        }
    }
}

// ---------------------------------------------------------------------------
// Flash attention v3 (unchanged — 161us).
// ---------------------------------------------------------------------------
#define FA_THREADS 256
#define SKT 64
#define QSTR 68
#define KSTR 68

#define OFF_Q  0
#define OFF_K0 8704
#define OFF_K1 13056
#define OFF_VT 17408
#define OFF_MR 21504
#define OFF_MS 21632
#define FA_SMEM_U32 21696
#define FA_SMEM_BYTES (FA_SMEM_U32 * 4)  // 86784

__device__ __forceinline__ int vt_idx(int d, int key) {
    int grp = (key >> 2) ^ (d & 7) ^ ((d >> 3) & 7);
    return d * 64 + grp * 4 + (key & 3);
}

__global__ __launch_bounds__(FA_THREADS, 2) void flash_mma_kernel(
    const float* __restrict__ Q, const float* __restrict__ K,
    const float* __restrict__ V, const int* __restrict__ mask,
    float* __restrict__ O)
{
    extern __shared__ uint32_t sm[];
    uint32_t* Qs = sm + OFF_Q;
    uint32_t* Vs = sm + OFF_VT;
    const int* mraw = (const int*)(sm + OFF_MR);
    float*   msf = (float*)(sm + OFF_MS);
    const uint32_t sb = smem_u32(sm);

    const int b  = blockIdx.z;
    const int h  = blockIdx.y;
    const int q0 = blockIdx.x * 128;
    const int tid = threadIdx.x;
    const int wid = tid >> 5;
    const int lane = tid & 31;
    const int lq = lane >> 2;
    const int lr = lane & 3;
    const int wm = wid * 16;

    const float C = 0.0450842200f;   // log2(e) / 32

    const uint32_t qa = sb + (uint32_t)(OFF_Q + (wm + (lane & 15)) * QSTR
                                        + ((lane >> 4) << 2)) * 4;
    const int krow = ((lane >> 4) << 3) + (lane & 7);
    const int kcol = ((lane >> 3) & 1) << 2;
    const int jj   = lane & 7;
    const int half = (lane >> 3) & 1;
    const int hv   = lane >> 4;
    const int dl   = 8 * hv + jj;
    const uint32_t vtb = sb + (uint32_t)OFF_VT * 4 + (uint32_t)dl * 256;

    // --- load Q tile (tf32, uint4 STS) ---
    const float* Qg = Q + ((size_t)b * SS + q0) * EE + h * DD;
#pragma unroll
    for (int it = 0; it < 8; it++) {
        int idx = tid + it * 256;
        int r = idx >> 4, c4 = (idx & 15) * 4;
        float4 v = *(const float4*)&Qg[(size_t)r * EE + c4];
        uint4 t;
        t.x = f2tf32(v.x); t.y = f2tf32(v.y); t.z = f2tf32(v.z); t.w = f2tf32(v.w);
        *(uint4*)&Qs[r * QSTR + c4] = t;
    }

    float o[8][4];
#pragma unroll
    for (int n = 0; n < 8; n++)
#pragma unroll
        for (int f = 0; f < 4; f++) o[n][f] = 0.f;

    float m0 = -1e30f, m1 = -1e30f, l0 = 0.f, l1 = 0.f;

    const float* Kg = K + (size_t)b * SS * EE + h * DD;
    const float* Vg = V + (size_t)b * SS * EE + h * DD;

    // prologue: cp.async stage 0 (K tile 0 + mask 0)
    {
#pragma unroll
        for (int it = 0; it < 4; it++) {
            int idx = tid + it * 256;
            int r = idx >> 4, c4 = (idx & 15) * 4;
            cp16(sb + (uint32_t)(OFF_K0 + r * KSTR + c4) * 4,
                 &Kg[(size_t)r * EE + c4]);
        }
        if (tid < 16)
            cp16(sb + (uint32_t)(OFF_MR + tid * 4) * 4,
                 &mask[b * SS + tid * 4]);
        cp_commit();
    }

#pragma unroll 1
    for (int t = 0; t < SS / SKT; t++) {
        const int s0 = t * SKT;
        if (t + 1 < SS / SKT) {
            const uint32_t kb = ((t + 1) & 1) ? OFF_K1 : OFF_K0;
#pragma unroll
            for (int it = 0; it < 4; it++) {
                int idx = tid + it * 256;
                int r = idx >> 4, c4 = (idx & 15) * 4;
                cp16(sb + (uint32_t)(kb + r * KSTR + c4) * 4,
                     &Kg[(size_t)(s0 + SKT + r) * EE + c4]);
            }
            if (tid < 16)
                cp16(sb + (uint32_t)(OFF_MR + ((t + 1) & 1) * 64 + tid * 4) * 4,
                     &mask[b * SS + s0 + SKT + tid * 4]);
            cp_commit();
        }
        if (t == SS / SKT - 1) cp_wait0(); else cp_wait1();
        __syncthreads();

        // --- loader: K in-place cvt, V transpose (permuted), msf ---
        const uint32_t kb = (t & 1) ? OFF_K1 : OFF_K0;
#pragma unroll
        for (int it = 0; it < 4; it++) {
            int idx = tid + it * 256;
            int r = idx >> 4, c4 = (idx & 15) * 4;
            uint4 kv = *(uint4*)&sm[kb + r * KSTR + c4];
            kv.x = f2tf32(__uint_as_float(kv.x));
            kv.y = f2tf32(__uint_as_float(kv.y));
            kv.z = f2tf32(__uint_as_float(kv.z));
            kv.w = f2tf32(__uint_as_float(kv.w));
            *(uint4*)&sm[kb + r * KSTR + c4] = kv;

            float4 vv = *(const float4*)&Vg[(size_t)(s0 + r) * EE + c4];
            const int kp = (r & ~7) | ((r & 1) << 2) | ((r >> 1) & 3);
            Vs[vt_idx(c4 + 0, kp)] = f2tf32(vv.x);
            Vs[vt_idx(c4 + 1, kp)] = f2tf32(vv.y);
            Vs[vt_idx(c4 + 2, kp)] = f2tf32(vv.z);
            Vs[vt_idx(c4 + 3, kp)] = f2tf32(vv.w);
        }
        if (tid < SKT) msf[tid] = mraw[(t & 1) * 64 + tid] ? 0.0f : -1e30f;
        __syncthreads();

        // --- scores S = Q . K^T ---
        const uint32_t ka = sb + (uint32_t)(kb + krow * KSTR + kcol) * 4;
        float s[8][4];
#pragma unroll
        for (int n = 0; n < 8; n++)
#pragma unroll
            for (int f = 0; f < 4; f++) s[n][f] = 0.f;

#pragma unroll
        for (int kk = 0; kk < 8; kk++) {
            uint32_t a[4];
            ldsm4(a[0], a[1], a[2], a[3], qa + kk * 32);
#pragma unroll
            for (int p = 0; p < 4; p++) {
                uint32_t bf0[2], bf1[2];
                ldsm4(bf0[0], bf0[1], bf1[0], bf1[1],
                      ka + (uint32_t)(p * 16 * KSTR) * 4 + kk * 32);
                mma_tf32(s[2 * p],     a, bf0);
                mma_tf32(s[2 * p + 1], a, bf1);
            }
        }

        // --- mask + scale (base-2 domain), tile row max ---
        float tmax0 = -1e30f, tmax1 = -1e30f;
#pragma unroll
        for (int n = 0; n < 8; n++) {
            const float mf0 = msf[n * 8 + 2 * lr];
            const float mf1 = msf[n * 8 + 2 * lr + 1];
            s[n][0] = fmaf(s[n][0], C, mf0);
            s[n][1] = fmaf(s[n][1], C, mf1);
            s[n][2] = fmaf(s[n][2], C, mf0);
            s[n][3] = fmaf(s[n][3], C, mf1);
            tmax0 = fmaxf(tmax0, fmaxf(s[n][0], s[n][1]));
            tmax1 = fmaxf(tmax1, fmaxf(s[n][2], s[n][3]));
        }
        tmax0 = fmaxf(tmax0, __shfl_xor_sync(0xffffffffu, tmax0, 1));
        tmax0 = fmaxf(tmax0, __shfl_xor_sync(0xffffffffu, tmax0, 2));
        tmax1 = fmaxf(tmax1, __shfl_xor_sync(0xffffffffu, tmax1, 1));
        tmax1 = fmaxf(tmax1, __shfl_xor_sync(0xffffffffu, tmax1, 2));

        const float mn0 = fmaxf(m0, tmax0);
        const float mn1 = fmaxf(m1, tmax1);
        const float c0 = fexp2(m0 - mn0);
        const float c1 = fexp2(m1 - mn1);
        m0 = mn0; m1 = mn1;
        l0 *= c0;  l1 *= c1;

        // --- p = 2^(s-m) in registers; rescale O; accumulate l ---
#pragma unroll
        for (int n = 0; n < 8; n++) {
            o[n][0] *= c0; o[n][1] *= c0; o[n][2] *= c1; o[n][3] *= c1;
            s[n][0] = fexp2(s[n][0] - m0);
            s[n][1] = fexp2(s[n][1] - m0);
            s[n][2] = fexp2(s[n][2] - m1);
            s[n][3] = fexp2(s[n][3] - m1);
            l0 += s[n][0] + s[n][1];
            l1 += s[n][2] + s[n][3];
        }

        // --- O += P . V  (A-frag from registers: {s0,s2,s1,s3}; V permuted) ---
#pragma unroll
        for (int kk = 0; kk < 8; kk++) {
            uint32_t a[4];
            a[0] = f2tf32(s[kk][0]);
            a[1] = f2tf32(s[kk][2]);
            a[2] = f2tf32(s[kk][1]);
            a[3] = f2tf32(s[kk][3]);
#pragma unroll
            for (int p = 0; p < 4; p++) {
                const int grp = (2 * kk + half) ^ jj ^ (2 * p + hv);
                uint32_t bf0[2], bf1[2];
                ldsm4(bf0[0], bf0[1], bf1[0], bf1[1],
                      vtb + (uint32_t)(p * 4096) + (uint32_t)(grp * 16));
                mma_tf32(o[2 * p],     a, bf0);
                mma_tf32(o[2 * p + 1], a, bf1);
            }
        }
    }

    // --- finalize ---
    l0 += __shfl_xor_sync(0xffffffffu, l0, 1);
    l0 += __shfl_xor_sync(0xffffffffu, l0, 2);
    l1 += __shfl_xor_sync(0xffffffffu, l1, 1);
    l1 += __shfl_xor_sync(0xffffffffu, l1, 2);
    const float inv0 = 1.0f / l0;
    const float inv1 = 1.0f / l1;

    float* Og = O + ((size_t)b * SS + q0 + wm + lq) * EE + h * DD;
#pragma unroll
    for (int n = 0; n < 8; n++) {
        *(float2*)&Og[n * 8 + 2 * lr] =
            make_float2(o[n][0] * inv0, o[n][1] * inv0);
        *(float2*)&Og[(size_t)8 * EE + n * 8 + 2 * lr] =
            make_float2(o[n][2] * inv1, o[n][3] * inv1);
    }
}

// ---------------------------------------------------------------------------
// Launch
// Inputs (metadata order): value, key_in, query, mask,
//                          Wq, bq, Wk, bk, Wv, bv, Wo, bo
// ---------------------------------------------------------------------------
extern "C" void kernel_launch(void* const* d_in, const int* in_sizes, int n_in,
                              void* d_out, int out_size)
{
    const float* value  = (const float*)d_in[0];
    const float* key_in = (const float*)d_in[1];
    const float* query  = (const float*)d_in[2];
    const int*   mask   = (const int*)  d_in[3];
    const float* Wq = (const float*)d_in[4];
    const float* bq = (const float*)d_in[5];
    const float* Wk = (const float*)d_in[6];
    const float* bk = (const float*)d_in[7];
    const float* Wv = (const float*)d_in[8];
    const float* bv = (const float*)d_in[9];
    const float* Wo = (const float*)d_in[10];
    const float* bo = (const float*)d_in[11];
    float* out = (float*)d_out;

    float *dQ, *dK, *dV, *dA;
    cudaGetSymbolAddress((void**)&dQ, g_Q);
    cudaGetSymbolAddress((void**)&dK, g_K);
    cudaGetSymbolAddress((void**)&dV, g_V);
    cudaGetSymbolAddress((void**)&dA, g_A);

    cudaFuncSetAttribute(gemm2_tf32,
                         cudaFuncAttributeMaxDynamicSharedMemorySize, G3_SMEM_BYTES);
    cudaFuncSetAttribute(flash_mma_kernel,
                         cudaFuncAttributeMaxDynamicSharedMemorySize, FA_SMEM_BYTES);

    const int M = BB * SS;   // 4096
    const int N = EE;        // 1024
    const int Kd = EE;       // 1024

    dim3 ggrid(N / BN3, M / BM3);   // (8, 32) = 256 CTAs

    gemm2_tf32<<<ggrid, 256, G3_SMEM_BYTES>>>(query,  Wq, bq, dQ, M, N, Kd);
    gemm2_tf32<<<ggrid, 256, G3_SMEM_BYTES>>>(key_in, Wk, bk, dK, M, N, Kd);
    gemm2_tf32<<<ggrid, 256, G3_SMEM_BYTES>>>(value,  Wv, bv, dV, M, N, Kd);

    dim3 fgrid(SS / 128, HH, BB);   // (8, 16, 4)
    flash_mma_kernel<<<fgrid, FA_THREADS, FA_SMEM_BYTES>>>(dQ, dK, dV, mask, dA);

    gemm2_tf32<<<ggrid, 256, G3_SMEM_BYTES>>>(dA, Wo, bo, out, M, N, Kd);
}

// round 17
// speedup vs baseline: 1.5744x; 1.5744x over previous
#include <cuda_runtime.h>
#include <cuda_fp16.h>
#include <cstdint>

// Problem shape (fixed): B=4, S=1024, E=1024, H=16, D=64
#define BB 4
#define SS 1024
#define EE 1024
#define HH 16
#define DD 64

// ---------------------------------------------------------------------------
// fp16 scratch (static __device__ globals — allocation-free per harness rules)
// ---------------------------------------------------------------------------
__device__ __half g_hXq[BB * SS * EE];
__device__ __half g_hXk[BB * SS * EE];
__device__ __half g_hXv[BB * SS * EE];
__device__ __half g_hWq[EE * EE];
__device__ __half g_hWk[EE * EE];
__device__ __half g_hWv[EE * EE];
__device__ __half g_hWo[EE * EE];
__device__ __half g_hQ[BB * SS * EE];
__device__ __half g_hK[BB * SS * EE];
__device__ __half g_hV[BB * SS * EE];
__device__ __half g_hA[BB * SS * EE];

// ---------------------------------------------------------------------------
// Helpers
// ---------------------------------------------------------------------------
__device__ __forceinline__ uint32_t smem_u32(const void* p) {
    uint32_t a;
    asm("{ .reg .u64 t; cvta.to.shared.u64 t, %1; cvt.u32.u64 %0, t; }"
        : "=r"(a) : "l"(p));
    return a;
}

__device__ __forceinline__ uint32_t packh2(float x, float y) {
    __half2 h = __floats2half2_rn(x, y);   // lo = x, hi = y
    return *(uint32_t*)&h;
}

// mma.sync m16n8k16 fp16: D(f32) += A(f16) * B(f16)
__device__ __forceinline__ void mma_f16(float* c, const uint32_t* a,
                                        uint32_t b0, uint32_t b1) {
    asm volatile(
        "mma.sync.aligned.m16n8k16.row.col.f32.f16.f16.f32 "
        "{%0,%1,%2,%3}, {%4,%5,%6,%7}, {%8,%9}, {%0,%1,%2,%3};"
        : "+f"(c[0]), "+f"(c[1]), "+f"(c[2]), "+f"(c[3])
        : "r"(a[0]), "r"(a[1]), "r"(a[2]), "r"(a[3]),
          "r"(b0), "r"(b1));
}

// ldmatrix x4 (non-trans b16): within each 8x8 fp16 matrix, lane l gets
// (row l>>2, fp16 cols 2(l&3), 2(l&3)+1) packed.
__device__ __forceinline__ void ldsm4(uint32_t& r0, uint32_t& r1,
                                      uint32_t& r2, uint32_t& r3, uint32_t addr) {
    asm volatile(
        "ldmatrix.sync.aligned.m8n8.x4.shared.b16 {%0,%1,%2,%3}, [%4];"
        : "=r"(r0), "=r"(r1), "=r"(r2), "=r"(r3) : "r"(addr));
}

// ldmatrix x4 TRANS: lane l gets (rows 2(l&3),2(l&3)+1, col l>>2) packed.
__device__ __forceinline__ void ldsm4t(uint32_t& r0, uint32_t& r1,
                                       uint32_t& r2, uint32_t& r3, uint32_t addr) {
    asm volatile(
        "ldmatrix.sync.aligned.m8n8.x4.trans.shared.b16 {%0,%1,%2,%3}, [%4];"
        : "=r"(r0), "=r"(r1), "=r"(r2), "=r"(r3) : "r"(addr));
}

__device__ __forceinline__ void cp16(uint32_t dst, const void* src) {
    asm volatile("cp.async.cg.shared.global [%0], [%1], 16;"
                 :: "r"(dst), "l"(src));
}
__device__ __forceinline__ void cp_commit() {
    asm volatile("cp.async.commit_group;");
}
__device__ __forceinline__ void cp_wait0() {
    asm volatile("cp.async.wait_group 0;" ::: "memory");
}
__device__ __forceinline__ void cp_wait1() {
    asm volatile("cp.async.wait_group 1;" ::: "memory");
}

// FMA-pipe exp2 for x <= 0 (clamped at -126). ~4e-5 abs err.
__device__ __forceinline__ float fexp2(float x) {
    x = fmaxf(x, -126.0f);
    float z = x + 12582912.0f;
    int   i = __float_as_int(z);
    float f = x - (z - 12582912.0f);
    float p = 9.6181e-3f;
    p = fmaf(p, f, 5.55041e-2f);
    p = fmaf(p, f, 2.402265e-1f);
    p = fmaf(p, f, 6.931472e-1f);
    p = fmaf(p, f, 1.0f);
    return __int_as_float(__float_as_int(p) + (i << 23));
}

// ---------------------------------------------------------------------------
// Pre-convert: fp32 -> fp16 (inputs x3, weights x4). Pure HBM-bound.
// ---------------------------------------------------------------------------
__global__ __launch_bounds__(256) void cvt_f16_3(
    const float* __restrict__ a, const float* __restrict__ b,
    const float* __restrict__ c,
    __half* __restrict__ oa, __half* __restrict__ ob, __half* __restrict__ oc)
{
    const float* in; __half* out;
    if (blockIdx.z == 0)      { in = a; out = oa; }
    else if (blockIdx.z == 1) { in = b; out = ob; }
    else                      { in = c; out = oc; }
    int i = (blockIdx.x * 256 + threadIdx.x) * 8;
    float4 x = *(const float4*)&in[i];
    float4 y = *(const float4*)&in[i + 4];
    __half2 h[4];
    h[0] = __floats2half2_rn(x.x, x.y);
    h[1] = __floats2half2_rn(x.z, x.w);
    h[2] = __floats2half2_rn(y.x, y.y);
    h[3] = __floats2half2_rn(y.z, y.w);
    *(uint4*)&out[i] = *(uint4*)h;
}

__global__ __launch_bounds__(256) void cvt_f16_4(
    const float* __restrict__ a, const float* __restrict__ b,
    const float* __restrict__ c, const float* __restrict__ d,
    __half* __restrict__ oa, __half* __restrict__ ob,
    __half* __restrict__ oc, __half* __restrict__ od)
{
    const float* in; __half* out;
    if (blockIdx.z == 0)      { in = a; out = oa; }
    else if (blockIdx.z == 1) { in = b; out = ob; }
    else if (blockIdx.z == 2) { in = c; out = oc; }
    else                      { in = d; out = od; }
    int i = (blockIdx.x * 256 + threadIdx.x) * 8;
    float4 x = *(const float4*)&in[i];
    float4 y = *(const float4*)&in[i + 4];
    __half2 h[4];
    h[0] = __floats2half2_rn(x.x, x.y);
    h[1] = __floats2half2_rn(x.z, x.w);
    h[2] = __floats2half2_rn(y.x, y.y);
    h[3] = __floats2half2_rn(y.z, y.w);
    *(uint4*)&out[i] = *(uint4*)h;
}

// ---------------------------------------------------------------------------
// fp16 GEMM:  Y[M,N] = Xh[M,K] @ Wh[N,K]^T + bias[N]
// CTA 256x128, 8 warps (4m x 2n) of 64x64. BK=32 (2 k16 chunks).
// cp.async fp16 TRIPLE buffer. No conversions anywhere in the loop.
// OUT_HALF selects fp16 (scratch) or fp32 (final d_out) stores.
// ---------------------------------------------------------------------------
#define BMh 256
#define BNh 128
#define BKh 32
#define LDH 40     // halfs; 8 rows walk banks 4r mod 32 -> conflict-free ldsm

#define GH_AB (BMh * LDH)            // 10240 halfs
#define GH_BB (BNh * LDH)            //  5120 halfs
#define GH_ST (GH_AB + GH_BB)        // 15360 halfs = 30720 B
#define GH_SMEM_BYTES (3 * GH_ST * 2)  // 92160 B

template <bool OUT_HALF>
__global__ __launch_bounds__(256) void gemm_f16(
    const __half* __restrict__ X, const __half* __restrict__ W,
    const float* __restrict__ bias, void* __restrict__ Yv,
    int M, int N, int K)
{
    extern __shared__ __half smh[];
    const uint32_t sb = smem_u32(smh);

    const int tid = threadIdx.x;
    const int wid = tid >> 5;
    const int lane = tid & 31;
    const int lq = lane >> 2;
    const int lr = lane & 3;

    const int wm = (wid >> 1) * 64;     // 0,64,128,192
    const int wn = (wid & 1) * 64;      // 0,64

    const int row0 = blockIdx.y * BMh;
    const int col0 = blockIdx.x * BNh;

    float c[4][8][4];
#pragma unroll
    for (int m = 0; m < 4; m++)
#pragma unroll
        for (int n = 0; n < 8; n++)
#pragma unroll
            for (int f = 0; f < 4; f++) c[m][n][f] = 0.f;

    // loader: 4 threads/row (32 halfs = 4 x 8)
    const int lrow = tid >> 2;          // 0..63
    const int lh   = (tid & 3) * 8;     // half offset 0,8,16,24

    // ldmatrix lane components (shared by A and B):
    const int rowL = (lane & 7) + ((lane >> 3) & 1) * 8;  // row within 16
    const int hCol = (lane >> 4) * 8;                     // k-half offset

    const int nstages = K / BKh;        // 32

    // prologue: stages 0,1
#pragma unroll
    for (int ps = 0; ps < 2; ps++) {
        const int k0 = ps * BKh;
        const uint32_t stb = sb + (uint32_t)(ps * GH_ST) * 2;
#pragma unroll
        for (int i = 0; i < 4; i++) {
            const int r = lrow + i * 64;
            cp16(stb + (uint32_t)(r * LDH + lh) * 2,
                 &X[(size_t)(row0 + r) * K + k0 + lh]);
        }
#pragma unroll
        for (int i = 0; i < 2; i++) {
            const int r = lrow + i * 64;
            cp16(stb + (uint32_t)(GH_AB + r * LDH + lh) * 2,
                 &W[(size_t)(col0 + r) * K + k0 + lh]);
        }
        cp_commit();
    }

    int cur = 0, nx2 = 2;
#pragma unroll 1
    for (int s = 0; s < nstages; s++) {
        if (s == nstages - 1) cp_wait0(); else cp_wait1();
        __syncthreads();

        if (s + 2 < nstages) {
            const int k0 = (s + 2) * BKh;
            const uint32_t stb = sb + (uint32_t)(nx2 * GH_ST) * 2;
#pragma unroll
            for (int i = 0; i < 4; i++) {
                const int r = lrow + i * 64;
                cp16(stb + (uint32_t)(r * LDH + lh) * 2,
                     &X[(size_t)(row0 + r) * K + k0 + lh]);
            }
#pragma unroll
            for (int i = 0; i < 2; i++) {
                const int r = lrow + i * 64;
                cp16(stb + (uint32_t)(GH_AB + r * LDH + lh) * 2,
                     &W[(size_t)(col0 + r) * K + k0 + lh]);
            }
            cp_commit();
        }

        const uint32_t abase = sb + (uint32_t)(cur * GH_ST) * 2;
        const uint32_t bbase = abase + (uint32_t)GH_AB * 2;

#pragma unroll
        for (int kk = 0; kk < 2; kk++) {
            uint32_t a[4][4], bq[4][4];
#pragma unroll
            for (int m = 0; m < 4; m++)
                ldsm4(a[m][0], a[m][1], a[m][2], a[m][3],
                      abase + (uint32_t)((wm + m * 16 + rowL) * LDH + kk * 16 + hCol) * 2);
#pragma unroll
            for (int p = 0; p < 4; p++)
                ldsm4(bq[p][0], bq[p][1], bq[p][2], bq[p][3],
                      bbase + (uint32_t)((wn + p * 16 + rowL) * LDH + kk * 16 + hCol) * 2);
#pragma unroll
            for (int m = 0; m < 4; m++)
#pragma unroll
                for (int p = 0; p < 4; p++) {
                    mma_f16(c[m][2 * p],     a[m], bq[p][0], bq[p][2]);
                    mma_f16(c[m][2 * p + 1], a[m], bq[p][1], bq[p][3]);
                }
        }

        cur = (cur == 2) ? 0 : cur + 1;
        nx2 = (nx2 == 2) ? 0 : nx2 + 1;
    }

    // epilogue: fused bias
#pragma unroll
    for (int m = 0; m < 4; m++) {
        const int r_lo = row0 + wm + m * 16 + lq;
        const int r_hi = r_lo + 8;
#pragma unroll
        for (int n = 0; n < 8; n++) {
            const int col = col0 + wn + n * 8 + lr * 2;
            const float b0 = bias[col];
            const float b1 = bias[col + 1];
            if (OUT_HALF) {
                __half* Y = (__half*)Yv;
                *(__half2*)&Y[(size_t)r_lo * N + col] =
                    __floats2half2_rn(c[m][n][0] + b0, c[m][n][1] + b1);
                *(__half2*)&Y[(size_t)r_hi * N + col] =
                    __floats2half2_rn(c[m][n][2] + b0, c[m][n][3] + b1);
            } else {
                float* Y = (float*)Yv;
                *(float2*)&Y[(size_t)r_lo * N + col] =
                    make_float2(c[m][n][0] + b0, c[m][n][1] + b1);
                *(float2*)&Y[(size_t)r_hi * N + col] =
                    make_float2(c[m][n][2] + b0, c[m][n][3] + b1);
            }
        }
    }
}

// ---------------------------------------------------------------------------
// fp16 flash attention.
// Q/K/V fp16 in gmem (GEMM outputs). All tiles via cp.async (triple-buffered
// K/V/mask, one __syncthreads per tile). QK: ldmatrix non-trans. PV: A-frags
// packed from softmax registers; V via ldmatrix.trans (row-major, no
// transpose pass). Output dA fp16.
// ---------------------------------------------------------------------------
#define FA_THREADS 256
#define SKT 64
#define FSTR 72    // halfs per row (Q/K/V); 8-row bank walk conflict-free

// offsets in halfs
#define OFF_Q   0                       // 128*72 = 9216
#define OFF_K   9216                    // 3 stages x 64*72 = 4608 each
#define OFF_V   (OFF_K + 3 * 4608)      // 23040
#define HALFS_TOTAL (OFF_V + 3 * 4608)  // 36864 halfs = 73728 B
#define OFF_MR_B (HALFS_TOTAL * 2)      // byte offset of mask raw (3 x 64 ints)
#define FA_SMEM_BYTES (OFF_MR_B + 3 * 64 * 4)   // 74496 B

__global__ __launch_bounds__(FA_THREADS, 2) void flash_f16_kernel(
    const __half* __restrict__ Q, const __half* __restrict__ K,
    const __half* __restrict__ V, const int* __restrict__ mask,
    __half* __restrict__ O)
{
    extern __shared__ __half smf[];
    const uint32_t sb = smem_u32(smf);
    const int* mraw = (const int*)((char*)smf + OFF_MR_B);

    const int b  = blockIdx.z;
    const int h  = blockIdx.y;
    const int q0 = blockIdx.x * 128;
    const int tid = threadIdx.x;
    const int wid = tid >> 5;
    const int lane = tid & 31;
    const int lq = lane >> 2;
    const int lr = lane & 3;
    const int wm = wid * 16;

    const float C = 0.0450842200f;   // log2(e) / 32

    // ldmatrix lane components
    const int rowL = (lane & 7) + ((lane >> 3) & 1) * 8;   // non-trans row-in-16
    const int hCol = (lane >> 4) * 8;                      // non-trans k-half
    const uint32_t qa = sb + (uint32_t)(OFF_Q + (wm + (lane & 15)) * FSTR + hCol) * 2;
    // trans-V lane components: key row bit from lane>>4, d offset bit from lane>>3
    const int vRowL = (lane & 7) + ((lane >> 4) & 1) * 8;
    const int vCol  = ((lane >> 3) & 1) * 8;

    const __half* Qg = Q + ((size_t)b * SS + q0) * EE + h * DD;
    const __half* Kg = K + (size_t)b * SS * EE + h * DD;
    const __half* Vg = V + (size_t)b * SS * EE + h * DD;

    // prologue: group 0 = Q + K/V/mask stage 0 ; group 1 = stage 1
    {
#pragma unroll
        for (int it = 0; it < 4; it++) {          // Q: 128 rows x 64 halfs
            int idx = tid + it * 256;
            int r = idx >> 3, hh = (idx & 7) * 8;
            cp16(sb + (uint32_t)(OFF_Q + r * FSTR + hh) * 2,
                 &Qg[(size_t)r * EE + hh]);
        }
#pragma unroll
        for (int it = 0; it < 2; it++) {          // K/V stage 0
            int idx = tid + it * 256;
            int r = idx >> 3, hh = (idx & 7) * 8;
            cp16(sb + (uint32_t)(OFF_K + r * FSTR + hh) * 2,
                 &Kg[(size_t)r * EE + hh]);
            cp16(sb + (uint32_t)(OFF_V + r * FSTR + hh) * 2,
                 &Vg[(size_t)r * EE + hh]);
        }
        if (tid < 16)
            cp16(sb + (uint32_t)(OFF_MR_B + tid * 16), &mask[b * SS + tid * 4]);
        cp_commit();
#pragma unroll
        for (int it = 0; it < 2; it++) {          // K/V stage 1
            int idx = tid + it * 256;
            int r = idx >> 3, hh = (idx & 7) * 8;
            cp16(sb + (uint32_t)(OFF_K + 4608 + r * FSTR + hh) * 2,
                 &Kg[(size_t)(SKT + r) * EE + hh]);
            cp16(sb + (uint32_t)(OFF_V + 4608 + r * FSTR + hh) * 2,
                 &Vg[(size_t)(SKT + r) * EE + hh]);
        }
        if (tid < 16)
            cp16(sb + (uint32_t)(OFF_MR_B + 256 + tid * 16),
                 &mask[b * SS + SKT + tid * 4]);
        cp_commit();
    }

    float o[8][4];
#pragma unroll
    for (int n = 0; n < 8; n++)
#pragma unroll
        for (int f = 0; f < 4; f++) o[n][f] = 0.f;

    float m0 = -1e30f, m1 = -1e30f, l0 = 0.f, l1 = 0.f;

    const int NT = SS / SKT;   // 16
#pragma unroll 1
    for (int t = 0; t < NT; t++) {
        if (t == NT - 1) cp_wait0(); else cp_wait1();
        __syncthreads();   // stage-t data visible; all warps done with tile t-1

        // prefetch t+2 (buffer (t+2)%3 was last read at tile t-1 — safe)
        if (t + 2 < NT) {
            const int st = (t + 2) % 3;
            const int s2 = (t + 2) * SKT;
#pragma unroll
            for (int it = 0; it < 2; it++) {
                int idx = tid + it * 256;
                int r = idx >> 3, hh = (idx & 7) * 8;
                cp16(sb + (uint32_t)(OFF_K + st * 4608 + r * FSTR + hh) * 2,
                     &Kg[(size_t)(s2 + r) * EE + hh]);
                cp16(sb + (uint32_t)(OFF_V + st * 4608 + r * FSTR + hh) * 2,
                     &Vg[(size_t)(s2 + r) * EE + hh]);
            }
            if (tid < 16)
                cp16(sb + (uint32_t)(OFF_MR_B + st * 256 + tid * 16),
                     &mask[b * SS + s2 + tid * 4]);
            cp_commit();
        }

        const int st = t % 3;
        const uint32_t kbase = sb + (uint32_t)(OFF_K + st * 4608) * 2;
        const uint32_t vbase = sb + (uint32_t)(OFF_V + st * 4608) * 2;
        const int* mr = mraw + st * 64;

        // --- scores S = Q . K^T  (16 q-rows x 64 keys per warp) ---
        float s[8][4];
#pragma unroll
        for (int n = 0; n < 8; n++)
#pragma unroll
            for (int f = 0; f < 4; f++) s[n][f] = 0.f;

#pragma unroll
        for (int kk = 0; kk < 4; kk++) {         // d in k16 chunks
            uint32_t a[4];
            ldsm4(a[0], a[1], a[2], a[3], qa + kk * 32);
#pragma unroll
            for (int p = 0; p < 4; p++) {
                uint32_t bq[4];
                ldsm4(bq[0], bq[1], bq[2], bq[3],
                      kbase + (uint32_t)((p * 16 + rowL) * FSTR + kk * 16 + hCol) * 2);
                mma_f16(s[2 * p],     a, bq[0], bq[2]);
                mma_f16(s[2 * p + 1], a, bq[1], bq[3]);
            }
        }

        // --- mask (inline from raw ints) + scale, tile row max ---
        float tmax0 = -1e30f, tmax1 = -1e30f;
#pragma unroll
        for (int n = 0; n < 8; n++) {
            const float mf0 = mr[n * 8 + 2 * lr]     ? 0.0f : -1e30f;
            const float mf1 = mr[n * 8 + 2 * lr + 1] ? 0.0f : -1e30f;
            s[n][0] = fmaf(s[n][0], C, mf0);
            s[n][1] = fmaf(s[n][1], C, mf1);
            s[n][2] = fmaf(s[n][2], C, mf0);
            s[n][3] = fmaf(s[n][3], C, mf1);
            tmax0 = fmaxf(tmax0, fmaxf(s[n][0], s[n][1]));
            tmax1 = fmaxf(tmax1, fmaxf(s[n][2], s[n][3]));
        }
        tmax0 = fmaxf(tmax0, __shfl_xor_sync(0xffffffffu, tmax0, 1));
        tmax0 = fmaxf(tmax0, __shfl_xor_sync(0xffffffffu, tmax0, 2));
        tmax1 = fmaxf(tmax1, __shfl_xor_sync(0xffffffffu, tmax1, 1));
        tmax1 = fmaxf(tmax1, __shfl_xor_sync(0xffffffffu, tmax1, 2));

        const float mn0 = fmaxf(m0, tmax0);
        const float mn1 = fmaxf(m1, tmax1);
        const float c0 = fexp2(m0 - mn0);
        const float c1 = fexp2(m1 - mn1);
        m0 = mn0; m1 = mn1;
        l0 *= c0;  l1 *= c1;

        // --- p = 2^(s-m); rescale O; accumulate l ---
#pragma unroll
        for (int n = 0; n < 8; n++) {
            o[n][0] *= c0; o[n][1] *= c0; o[n][2] *= c1; o[n][3] *= c1;
            s[n][0] = fexp2(s[n][0] - m0);
            s[n][1] = fexp2(s[n][1] - m0);
            s[n][2] = fexp2(s[n][2] - m1);
            s[n][3] = fexp2(s[n][3] - m1);
            l0 += s[n][0] + s[n][1];
            l1 += s[n][2] + s[n][3];
        }

        // --- O += P . V  (A packed from regs; V via ldmatrix.trans) ---
#pragma unroll
        for (int kk = 0; kk < 4; kk++) {         // keys in k16 chunks
            uint32_t a[4];
            a[0] = packh2(s[2 * kk][0],     s[2 * kk][1]);
            a[1] = packh2(s[2 * kk][2],     s[2 * kk][3]);
            a[2] = packh2(s[2 * kk + 1][0], s[2 * kk + 1][1]);
            a[3] = packh2(s[2 * kk + 1][2], s[2 * kk + 1][3]);
#pragma unroll
            for (int p = 0; p < 4; p++) {
                uint32_t bv[4];
                ldsm4t(bv[0], bv[1], bv[2], bv[3],
                       vbase + (uint32_t)((kk * 16 + vRowL) * FSTR + p * 16 + vCol) * 2);
                mma_f16(o[2 * p],     a, bv[0], bv[2]);
                mma_f16(o[2 * p + 1], a, bv[1], bv[3]);
            }
        }
    }

    // --- finalize: quad-sum l, divide, store fp16 ---
    l0 += __shfl_xor_sync(0xffffffffu, l0, 1);
    l0 += __shfl_xor_sync(0xffffffffu, l0, 2);
    l1 += __shfl_xor_sync(0xffffffffu, l1, 1);
    l1 += __shfl_xor_sync(0xffffffffu, l1, 2);
    const float inv0 = 1.0f / l0;
    const float inv1 = 1.0f / l1;

    __half* Og = O + ((size_t)b * SS + q0 + wm + lq) * EE + h * DD;
#pragma unroll
    for (int n = 0; n < 8; n++) {
        *(__half2*)&Og[n * 8 + 2 * lr] =
            __floats2half2_rn(o[n][0] * inv0, o[n][1] * inv0);
        *(__half2*)&Og[(size_t)8 * EE + n * 8 + 2 * lr] =
            __floats2half2_rn(o[n][2] * inv1, o[n][3] * inv1);
    }
}

// ---------------------------------------------------------------------------
// Launch
// Inputs (metadata order): value, key_in, query, mask,
//                          Wq, bq, Wk, bk, Wv, bv, Wo, bo
// ---------------------------------------------------------------------------
extern "C" void kernel_launch(void* const* d_in, const int* in_sizes, int n_in,
                              void* d_out, int out_size)
{
    const float* value  = (const float*)d_in[0];
    const float* key_in = (const float*)d_in[1];
    const float* query  = (const float*)d_in[2];
    const int*   mask   = (const int*)  d_in[3];
    const float* Wq = (const float*)d_in[4];
    const float* bq = (const float*)d_in[5];
    const float* Wk = (const float*)d_in[6];
    const float* bk = (const float*)d_in[7];
    const float* Wv = (const float*)d_in[8];
    const float* bv = (const float*)d_in[9];
    const float* Wo = (const float*)d_in[10];
    const float* bo = (const float*)d_in[11];
    float* out = (float*)d_out;

    __half *hXq, *hXk, *hXv, *hWq, *hWk, *hWv, *hWo, *hQ, *hK, *hV, *hA;
    cudaGetSymbolAddress((void**)&hXq, g_hXq);
    cudaGetSymbolAddress((void**)&hXk, g_hXk);
    cudaGetSymbolAddress((void**)&hXv, g_hXv);
    cudaGetSymbolAddress((void**)&hWq, g_hWq);
    cudaGetSymbolAddress((void**)&hWk, g_hWk);
    cudaGetSymbolAddress((void**)&hWv, g_hWv);
    cudaGetSymbolAddress((void**)&hWo, g_hWo);
    cudaGetSymbolAddress((void**)&hQ,  g_hQ);
    cudaGetSymbolAddress((void**)&hK,  g_hK);
    cudaGetSymbolAddress((void**)&hV,  g_hV);
    cudaGetSymbolAddress((void**)&hA,  g_hA);

    cudaFuncSetAttribute(gemm_f16<true>,
                         cudaFuncAttributeMaxDynamicSharedMemorySize, GH_SMEM_BYTES);
    cudaFuncSetAttribute(gemm_f16<false>,
                         cudaFuncAttributeMaxDynamicSharedMemorySize, GH_SMEM_BYTES);
    cudaFuncSetAttribute(flash_f16_kernel,
                         cudaFuncAttributeMaxDynamicSharedMemorySize, FA_SMEM_BYTES);

    const int M = BB * SS;   // 4096
    const int N = EE;        // 1024
    const int Kd = EE;       // 1024

    // pre-convert inputs + weights to fp16
    cvt_f16_3<<<dim3((M * EE) / 2048, 1, 3), 256>>>(
        query, key_in, value, hXq, hXk, hXv);
    cvt_f16_4<<<dim3((EE * EE) / 2048, 1, 4), 256>>>(
        Wq, Wk, Wv, Wo, hWq, hWk, hWv, hWo);

    dim3 ggrid(N / BNh, M / BMh);   // (8, 16) = 128 CTAs

    gemm_f16<true><<<ggrid, 256, GH_SMEM_BYTES>>>(hXq, hWq, bq, hQ, M, N, Kd);
    gemm_f16<true><<<ggrid, 256, GH_SMEM_BYTES>>>(hXk, hWk, bk, hK, M, N, Kd);
    gemm_f16<true><<<ggrid, 256, GH_SMEM_BYTES>>>(hXv, hWv, bv, hV, M, N, Kd);

    dim3 fgrid(SS / 128, HH, BB);   // (8, 16, 4)
    flash_f16_kernel<<<fgrid, FA_THREADS, FA_SMEM_BYTES>>>(hQ, hK, hV, mask, hA);

    gemm_f16<false><<<ggrid, 256, GH_SMEM_BYTES>>>(hA, hWo, bo, out, M, N, Kd);
}